// round 13
// baseline (speedup 1.0000x reference)
#include <cuda_runtime.h>
#include <cuda_bf16.h>
#include <cstdint>

#define MAX_NODES 100000
#define INDIM 128

typedef unsigned long long u64;

// Scratch: per-node projections P[n][0:64]=z@W1a, P[n][64:128]=z@W1b (bias-free)
__device__ float g_P[MAX_NODES * 128];

#define WK_PITCH 136

// ---------------------------------------------------------------------------
// f32x2 packed helpers
__device__ __forceinline__ u64 pack2(float lo, float hi) {
    u64 r; asm("mov.b64 %0, {%1, %2};" : "=l"(r) : "f"(lo), "f"(hi)); return r;
}
__device__ __forceinline__ void unpack2(u64 v, float& lo, float& hi) {
    asm("mov.b64 {%0, %1}, %2;" : "=f"(lo), "=f"(hi) : "l"(v));
}
__device__ __forceinline__ u64 fadd2(u64 a, u64 b) {
    u64 r; asm("add.rn.f32x2 %0, %1, %2;" : "=l"(r) : "l"(a), "l"(b)); return r;
}

// ---------------------------------------------------------------------------
// warp-MMA helpers (baseline PTX, plain sm_103 target)
__device__ __forceinline__ void mma_bf16(float* d,
                                         uint32_t a0, uint32_t a1, uint32_t a2, uint32_t a3,
                                         uint32_t b0, uint32_t b1) {
    asm volatile(
        "mma.sync.aligned.m16n8k16.row.col.f32.bf16.bf16.f32 "
        "{%0,%1,%2,%3}, {%4,%5,%6,%7}, {%8,%9}, {%0,%1,%2,%3};"
        : "+f"(d[0]), "+f"(d[1]), "+f"(d[2]), "+f"(d[3])
        : "r"(a0), "r"(a1), "r"(a2), "r"(a3), "r"(b0), "r"(b1));
}
__device__ __forceinline__ void ldmatrix_x4(uint32_t& r0, uint32_t& r1,
                                            uint32_t& r2, uint32_t& r3, uint32_t addr) {
    asm volatile("ldmatrix.sync.aligned.m8n8.x4.shared.b16 {%0,%1,%2,%3}, [%4];"
                 : "=r"(r0), "=r"(r1), "=r"(r2), "=r"(r3) : "r"(addr));
}
__device__ __forceinline__ uint32_t smem_u32(const void* p) {
    uint32_t a;
    asm("{ .reg .u64 t; cvta.to.shared.u64 t, %1; cvt.u32.u64 %0, t; }" : "=r"(a) : "l"(p));
    return a;
}
__device__ __forceinline__ uint32_t bf2(float x, float y) {  // lo=x, hi=y
    __nv_bfloat162 t = __floats2bfloat162_rn(x, y);
    uint32_t r; asm("mov.b32 %0, %1;" : "=r"(r) : "r"(*(uint32_t*)&t)); return r;
}
__device__ __forceinline__ void bf16_split(float x, float y, uint32_t& hi, uint32_t& lo) {
    hi = bf2(x, y);
    float hx = __uint_as_float(hi << 16);
    float hy = __uint_as_float(hi & 0xffff0000u);
    lo = bf2(x - hx, y - hy);
}

// ---------------------------------------------------------------------------
// Precompute via warp-level bf16 MMA. W images built in-block from W1
// (no separate prep kernel).
#define WIMG_BYTES (128 * WK_PITCH * 2)
#define SMEM_PRE   (2 * WIMG_BYTES)

__global__ __launch_bounds__(256) void precompute_mma_kernel(
    const float* __restrict__ z, const float* __restrict__ W1, int n_nodes)
{
    extern __shared__ __align__(16) char dsm[];
    __nv_bfloat16* swh = (__nv_bfloat16*)dsm;
    __nv_bfloat16* swl = (__nv_bfloat16*)(dsm + WIMG_BYTES);

    const int tid  = threadIdx.x;
    const int wid  = tid >> 5;
    const int lane = tid & 31;
    const int g    = lane >> 2;
    const int tg   = lane & 3;
    const int nb   = blockIdx.x * 128;
    const int r0   = wid * 16;

    // Build W^T bf16 hi/lo images directly from W1 (L2-cached across blocks)
    for (int idx = tid; idx < 128 * 128; idx += 256) {
        int n = idx >> 7, k = idx & 127;
        float v = (n < 64) ? W1[k * 64 + n] : W1[(128 + k) * 64 + (n - 64)];
        __nv_bfloat16 h = __float2bfloat16_rn(v);
        __nv_bfloat16 l = __float2bfloat16_rn(v - __bfloat162float(h));
        swh[n * WK_PITCH + k] = h;
        swl[n * WK_PITCH + k] = l;
    }
    __syncthreads();

    const int nloc   = (lane & 7) + ((lane >> 4) << 3);
    const int koff16 = (lane >> 3) & 1;
    const uint32_t aWH = smem_u32(swh) + (uint32_t)nloc * (WK_PITCH * 2) + (uint32_t)koff16 * 16;
    const uint32_t aWL = smem_u32(swl) + (uint32_t)nloc * (WK_PITCH * 2) + (uint32_t)koff16 * 16;

    int rowA = nb + r0 + g;
    int rowB = rowA + 8;
    const int rA = (rowA < n_nodes) ? rowA : 0;
    const int rB = (rowB < n_nodes) ? rowB : 0;
    const float* zA = z + (size_t)rA * 128 + 2 * tg;
    const float* zB = z + (size_t)rB * 128 + 2 * tg;

    float acc[16][4];
#pragma unroll
    for (int t = 0; t < 16; t++)
#pragma unroll
        for (int u = 0; u < 4; u++) acc[t][u] = 0.f;

    float2 raw0 = *(const float2*)(zA + 0);
    float2 raw1 = *(const float2*)(zB + 0);
    float2 raw2 = *(const float2*)(zA + 8);
    float2 raw3 = *(const float2*)(zB + 8);

#pragma unroll
    for (int ks = 0; ks < 8; ks++) {
        float2 n0v, n1v, n2v, n3v;
        if (ks < 7) {
            n0v = *(const float2*)(zA + 16 * (ks + 1));
            n1v = *(const float2*)(zB + 16 * (ks + 1));
            n2v = *(const float2*)(zA + 16 * (ks + 1) + 8);
            n3v = *(const float2*)(zB + 16 * (ks + 1) + 8);
        }
        uint32_t ah0, al0, ah1, al1, ah2, al2, ah3, al3;
        bf16_split(raw0.x, raw0.y, ah0, al0);
        bf16_split(raw1.x, raw1.y, ah1, al1);
        bf16_split(raw2.x, raw2.y, ah2, al2);
        bf16_split(raw3.x, raw3.y, ah3, al3);

        const uint32_t kadd = (uint32_t)ks * 32;
#pragma unroll
        for (int tp = 0; tp < 8; tp++) {
            const uint32_t toff = (uint32_t)tp * (16 * WK_PITCH * 2) + kadd;
            uint32_t wb0, wb1, wb2, wb3, vb0, vb1, vb2, vb3;
            ldmatrix_x4(wb0, wb1, wb2, wb3, aWH + toff);
            ldmatrix_x4(vb0, vb1, vb2, vb3, aWL + toff);
            float* d0 = acc[2 * tp];
            float* d1 = acc[2 * tp + 1];
            mma_bf16(d0, ah0, ah1, ah2, ah3, wb0, wb1);
            mma_bf16(d1, ah0, ah1, ah2, ah3, wb2, wb3);
            mma_bf16(d0, al0, al1, al2, al3, wb0, wb1);
            mma_bf16(d1, al0, al1, al2, al3, wb2, wb3);
            mma_bf16(d0, ah0, ah1, ah2, ah3, vb0, vb1);
            mma_bf16(d1, ah0, ah1, ah2, ah3, vb2, vb3);
        }
        raw0 = n0v; raw1 = n1v; raw2 = n2v; raw3 = n3v;
    }

    if (rowA < n_nodes) {
        float* dst = g_P + (size_t)rowA * 128 + 2 * tg;
#pragma unroll
        for (int t = 0; t < 16; t++)
            *(float2*)(dst + 8 * t) = make_float2(acc[t][0], acc[t][1]);
    }
    if (rowB < n_nodes) {
        float* dst = g_P + (size_t)rowB * 128 + 2 * tg;
#pragma unroll
        for (int t = 0; t < 16; t++)
            *(float2*)(dst + 8 * t) = make_float2(acc[t][2], acc[t][3]);
    }
}

// ---------------------------------------------------------------------------
// Edge kernel: layer 2 on tensor cores (3-pass bf16 hi/lo).
#define HPITCHB 144      // bytes per H row (72 bf16)
__global__ __launch_bounds__(256, 2) void edge_kernel(
    const void* __restrict__ eidx,
    const float* __restrict__ W2, const float* __restrict__ b2,
    const float* __restrict__ W3, const float* __restrict__ b3,
    const float* __restrict__ b1,
    float* __restrict__ out, int E)
{
    __shared__ __align__(16) __nv_bfloat16 Hh[8][32 * 72];
    __shared__ __align__(16) __nv_bfloat16 Hl[8][32 * 72];
    __shared__ __align__(16) uint32_t whf[1024];
    __shared__ __align__(16) uint32_t wlf[1024];
    __shared__ float w3s[32], b2sm[32];

    const int tid  = threadIdx.x;
    const int lane = tid & 31;
    const int wid  = tid >> 5;
    const int g    = lane >> 2;
    const int tg   = lane & 3;
    const int gw   = (blockIdx.x * blockDim.x + tid) >> 5;
    const int GW   = (gridDim.x * blockDim.x) >> 5;
    const int STRIDE = GW * 32;

    for (int id = tid; id < 1024; id += 256) {
        int l2 = id & 31;
        int r  = (id >> 5) & 1;
        int nt = (id >> 6) & 3;
        int kt = id >> 8;
        int k0 = kt * 16 + 2 * (l2 & 3) + r * 8;
        int n  = nt * 8 + (l2 >> 2);
        float v0 = W2[k0 * 32 + n];
        float v1 = W2[(k0 + 1) * 32 + n];
        uint32_t hi, lo;
        bf16_split(v0, v1, hi, lo);
        whf[id] = hi;
        wlf[id] = lo;
    }
    if (tid < 32) {
        w3s[tid]  = W3[tid];
        b2sm[tid] = b2[tid];
    }
    const float b3v = b3[0];
    const u64 b1p = pack2(b1[2 * lane], b1[2 * lane + 1]);

    const int* ei32 = (const int*)eidx;
    int oddw = ei32[2 * lane + 1] | ei32[2 * lane + 65];
    const bool is64 = (__ballot_sync(0xffffffffu, oddw != 0) == 0u);

    const char* __restrict__ Pb = (const char*)g_P;
    const unsigned lane8 = (unsigned)lane * 8u;
    const int Em1 = E - 1;

    __syncthreads();

    char* __restrict__ Hhw = (char*)&Hh[wid][0];
    char* __restrict__ Hlw = (char*)&Hl[wid][0];
    const uint32_t lbase = (uint32_t)(lane & 15) * HPITCHB + (uint32_t)(lane >> 4) * 16;
    const uint32_t aHh = smem_u32(Hhw) + lbase;
    const uint32_t aHl = smem_u32(Hlw) + lbase;

    float b2q[4][2], w3q[4][2];
#pragma unroll
    for (int nt = 0; nt < 4; nt++)
#pragma unroll
        for (int r = 0; r < 2; r++) {
            int col = nt * 8 + 2 * tg + r;
            b2q[nt][r] = b2sm[col];
            w3q[nt][r] = w3s[col];
        }

    for (int b = gw * 32; b < E; b += STRIDE) {
        // ---- batch index load (coalesced, clamped, PRE-SCALED to byte offs) ----
        int me = min(b + lane, Em1);
        int iS, jS;
        if (is64) {
            iS = (int)((const long long*)eidx)[me] * 512;
            jS = (int)((const long long*)eidx)[(long long)E + me] * 512 + 256;
        } else {
            iS = ((const int*)eidx)[me] * 512;
            jS = ((const int*)eidx)[E + me] * 512 + 256;
        }

        // ---- phase 1: gather + layer1 + bf16 split, 1-group prefetch ----
        u64 pa[4], pb[4];
#pragma unroll
        for (int t = 0; t < 4; t++) {
            unsigned ii = (unsigned)__shfl_sync(0xffffffffu, iS, t);
            unsigned jj = (unsigned)__shfl_sync(0xffffffffu, jS, t);
            pa[t] = *(const u64*)(Pb + ii + lane8);
            pb[t] = *(const u64*)(Pb + jj + lane8);
        }
#pragma unroll
        for (int gq = 0; gq < 8; gq++) {
            u64 npa[4], npb[4];
            if (gq < 7) {
#pragma unroll
                for (int t = 0; t < 4; t++) {
                    int en = (gq + 1) * 4 + t;
                    unsigned ii = (unsigned)__shfl_sync(0xffffffffu, iS, en);
                    unsigned jj = (unsigned)__shfl_sync(0xffffffffu, jS, en);
                    npa[t] = *(const u64*)(Pb + ii + lane8);
                    npb[t] = *(const u64*)(Pb + jj + lane8);
                }
            }
#pragma unroll
            for (int t = 0; t < 4; t++) {
                float hx, hy;
                unpack2(fadd2(fadd2(pa[t], pb[t]), b1p), hx, hy);
                hx = fmaxf(hx, 0.f);
                hy = fmaxf(hy, 0.f);
                uint32_t hi, lo;
                bf16_split(hx, hy, hi, lo);
                int e = gq * 4 + t;
                *(uint32_t*)(Hhw + e * HPITCHB + lane * 4) = hi;
                *(uint32_t*)(Hlw + e * HPITCHB + lane * 4) = lo;
            }
            if (gq < 7) {
#pragma unroll
                for (int t = 0; t < 4; t++) { pa[t] = npa[t]; pb[t] = npb[t]; }
            }
        }
        __syncwarp();

        // ---- phase 2: 32x32x64 GEMM on tensor cores (3-pass) ----
        float D[2][4][4];
#pragma unroll
        for (int mt = 0; mt < 2; mt++)
#pragma unroll
            for (int nt = 0; nt < 4; nt++)
#pragma unroll
                for (int u = 0; u < 4; u++) D[mt][nt][u] = 0.f;

#pragma unroll
        for (int kt = 0; kt < 4; kt++) {
            uint32_t ah[2][4], al[2][4];
            ldmatrix_x4(ah[0][0], ah[0][1], ah[0][2], ah[0][3], aHh + kt * 32);
            ldmatrix_x4(ah[1][0], ah[1][1], ah[1][2], ah[1][3], aHh + 16 * HPITCHB + kt * 32);
            ldmatrix_x4(al[0][0], al[0][1], al[0][2], al[0][3], aHl + kt * 32);
            ldmatrix_x4(al[1][0], al[1][1], al[1][2], al[1][3], aHl + 16 * HPITCHB + kt * 32);
            uint32_t bh[4][2], bl[4][2];
#pragma unroll
            for (int nt = 0; nt < 4; nt++) {
                bh[nt][0] = whf[((kt * 4 + nt) * 2 + 0) * 32 + lane];
                bh[nt][1] = whf[((kt * 4 + nt) * 2 + 1) * 32 + lane];
                bl[nt][0] = wlf[((kt * 4 + nt) * 2 + 0) * 32 + lane];
                bl[nt][1] = wlf[((kt * 4 + nt) * 2 + 1) * 32 + lane];
            }
#pragma unroll
            for (int mt = 0; mt < 2; mt++)
#pragma unroll
                for (int nt = 0; nt < 4; nt++) {
                    mma_bf16(D[mt][nt], ah[mt][0], ah[mt][1], ah[mt][2], ah[mt][3],
                             bh[nt][0], bh[nt][1]);
                    mma_bf16(D[mt][nt], al[mt][0], al[mt][1], al[mt][2], al[mt][3],
                             bh[nt][0], bh[nt][1]);
                    mma_bf16(D[mt][nt], ah[mt][0], ah[mt][1], ah[mt][2], ah[mt][3],
                             bl[nt][0], bl[nt][1]);
                }
        }

        // ---- phase 3: bias+relu, dot w3, 4-lane reduce, sigmoid, store ----
        float part[4] = {0.f, 0.f, 0.f, 0.f};
#pragma unroll
        for (int mt = 0; mt < 2; mt++)
#pragma unroll
            for (int nt = 0; nt < 4; nt++) {
                const float* c = D[mt][nt];
                part[mt * 2 + 0] = fmaf(fmaxf(c[0] + b2q[nt][0], 0.f), w3q[nt][0],
                                   fmaf(fmaxf(c[1] + b2q[nt][1], 0.f), w3q[nt][1],
                                        part[mt * 2 + 0]));
                part[mt * 2 + 1] = fmaf(fmaxf(c[2] + b2q[nt][0], 0.f), w3q[nt][0],
                                   fmaf(fmaxf(c[3] + b2q[nt][1], 0.f), w3q[nt][1],
                                        part[mt * 2 + 1]));
            }
#pragma unroll
        for (int t = 0; t < 4; t++) {
            part[t] += __shfl_xor_sync(0xffffffffu, part[t], 1);
            part[t] += __shfl_xor_sync(0xffffffffu, part[t], 2);
        }
        if (tg == 0) {
#pragma unroll
            for (int t = 0; t < 4; t++) {
                int row = g + t * 8;
                if (b + row < E) {
                    float sig = __fdividef(1.f, 1.f + __expf(-(part[t] + b3v)));
                    out[b + row] = sig;
                }
            }
        }
        __syncwarp();
    }
}

// ---------------------------------------------------------------------------
extern "C" void kernel_launch(void* const* d_in, const int* in_sizes, int n_in,
                              void* d_out, int out_size)
{
    const float* z  = (const float*)d_in[0];
    const void*  ei = d_in[1];
    const float* W1 = (const float*)d_in[2];
    const float* b1 = (const float*)d_in[3];
    const float* W2 = (const float*)d_in[4];
    const float* b2 = (const float*)d_in[5];
    const float* W3 = (const float*)d_in[6];
    const float* b3 = (const float*)d_in[7];
    float* out = (float*)d_out;

    int n_nodes = in_sizes[0] / INDIM;
    if (n_nodes > MAX_NODES) n_nodes = MAX_NODES;
    int E = out_size;

    cudaFuncSetAttribute(precompute_mma_kernel,
                         cudaFuncAttributeMaxDynamicSharedMemorySize, SMEM_PRE);

    int gblocks = (n_nodes + 127) / 128;
    precompute_mma_kernel<<<gblocks, 256, SMEM_PRE>>>(z, W1, n_nodes);
    edge_kernel<<<296, 256>>>(ei, W2, b2, W3, b3, b1, out, E);
}

// round 14
// speedup vs baseline: 1.3922x; 1.3922x over previous
#include <cuda_runtime.h>
#include <cuda_bf16.h>
#include <cstdint>

#define MAX_NODES 100000
#define INDIM 128

typedef unsigned long long u64;

// Scratch: per-node projections P[n][0:64]=z@W1a+b1, P[n][64:128]=z@W1b
__device__ float g_P[MAX_NODES * 128];
// W^T images, bf16 hi/lo, [n=128][k pitch 136]
#define WK_PITCH 136
__device__ __align__(16) __nv_bfloat16 g_wh[128 * WK_PITCH];
__device__ __align__(16) __nv_bfloat16 g_wl[128 * WK_PITCH];

// ---------------------------------------------------------------------------
// f32x2 packed helpers
__device__ __forceinline__ u64 pack2(float lo, float hi) {
    u64 r; asm("mov.b64 %0, {%1, %2};" : "=l"(r) : "f"(lo), "f"(hi)); return r;
}
__device__ __forceinline__ void unpack2(u64 v, float& lo, float& hi) {
    asm("mov.b64 {%0, %1}, %2;" : "=f"(lo), "=f"(hi) : "l"(v));
}
__device__ __forceinline__ u64 fadd2(u64 a, u64 b) {
    u64 r; asm("add.rn.f32x2 %0, %1, %2;" : "=l"(r) : "l"(a), "l"(b)); return r;
}

// ---------------------------------------------------------------------------
// warp-MMA helpers (baseline PTX, plain sm_103 target)
__device__ __forceinline__ void mma_bf16(float* d,
                                         uint32_t a0, uint32_t a1, uint32_t a2, uint32_t a3,
                                         uint32_t b0, uint32_t b1) {
    asm volatile(
        "mma.sync.aligned.m16n8k16.row.col.f32.bf16.bf16.f32 "
        "{%0,%1,%2,%3}, {%4,%5,%6,%7}, {%8,%9}, {%0,%1,%2,%3};"
        : "+f"(d[0]), "+f"(d[1]), "+f"(d[2]), "+f"(d[3])
        : "r"(a0), "r"(a1), "r"(a2), "r"(a3), "r"(b0), "r"(b1));
}
__device__ __forceinline__ void ldmatrix_x4(uint32_t& r0, uint32_t& r1,
                                            uint32_t& r2, uint32_t& r3, uint32_t addr) {
    asm volatile("ldmatrix.sync.aligned.m8n8.x4.shared.b16 {%0,%1,%2,%3}, [%4];"
                 : "=r"(r0), "=r"(r1), "=r"(r2), "=r"(r3) : "r"(addr));
}
__device__ __forceinline__ uint32_t smem_u32(const void* p) {
    uint32_t a;
    asm("{ .reg .u64 t; cvta.to.shared.u64 t, %1; cvt.u32.u64 %0, t; }" : "=r"(a) : "l"(p));
    return a;
}
__device__ __forceinline__ uint32_t bf2(float x, float y) {  // lo=x, hi=y
    __nv_bfloat162 t = __floats2bfloat162_rn(x, y);
    uint32_t r; asm("mov.b32 %0, %1;" : "=r"(r) : "r"(*(uint32_t*)&t)); return r;
}
__device__ __forceinline__ void bf16_split(float x, float y, uint32_t& hi, uint32_t& lo) {
    hi = bf2(x, y);
    float hx = __uint_as_float(hi << 16);
    float hy = __uint_as_float(hi & 0xffff0000u);
    lo = bf2(x - hx, y - hy);
}

// ---------------------------------------------------------------------------
// One-shot W1 prep (parallel): W^T bf16 hi/lo images (Wnk[n][k] = Wcat[k][n])
__global__ void w_prep_kernel(const float* __restrict__ W1) {
    int idx = blockIdx.x * 256 + threadIdx.x;
    if (idx < 128 * 128) {
        int n = idx >> 7, k = idx & 127;
        float v = (n < 64) ? W1[k * 64 + n] : W1[(128 + k) * 64 + (n - 64)];
        __nv_bfloat16 h = __float2bfloat16_rn(v);
        __nv_bfloat16 l = __float2bfloat16_rn(v - __bfloat162float(h));
        g_wh[n * WK_PITCH + k] = h;
        g_wl[n * WK_PITCH + k] = l;
    }
}

// ---------------------------------------------------------------------------
// Precompute via warp-level bf16 MMA; b1 folded into epilogue (cols < 64).
#define WIMG_BYTES (128 * WK_PITCH * 2)
#define SMEM_PRE   (2 * WIMG_BYTES)

__global__ __launch_bounds__(256) void precompute_mma_kernel(
    const float* __restrict__ z, const float* __restrict__ b1, int n_nodes)
{
    extern __shared__ __align__(16) char dsm[];
    __nv_bfloat16* swh = (__nv_bfloat16*)dsm;
    __nv_bfloat16* swl = (__nv_bfloat16*)(dsm + WIMG_BYTES);

    const int tid  = threadIdx.x;
    const int wid  = tid >> 5;
    const int lane = tid & 31;
    const int g    = lane >> 2;
    const int tg   = lane & 3;
    const int nb   = blockIdx.x * 128;
    const int r0   = wid * 16;

    {
        const float4* sh = (const float4*)g_wh;
        const float4* sl = (const float4*)g_wl;
        float4* dh = (float4*)swh;
        float4* dl = (float4*)swl;
        for (int i = tid; i < WIMG_BYTES / 16; i += 256) { dh[i] = sh[i]; dl[i] = sl[i]; }
    }
    __syncthreads();

    const int nloc   = (lane & 7) + ((lane >> 4) << 3);
    const int koff16 = (lane >> 3) & 1;
    const uint32_t aWH = smem_u32(swh) + (uint32_t)nloc * (WK_PITCH * 2) + (uint32_t)koff16 * 16;
    const uint32_t aWL = smem_u32(swl) + (uint32_t)nloc * (WK_PITCH * 2) + (uint32_t)koff16 * 16;

    int rowA = nb + r0 + g;
    int rowB = rowA + 8;
    const int rA = (rowA < n_nodes) ? rowA : 0;
    const int rB = (rowB < n_nodes) ? rowB : 0;
    const float* zA = z + (size_t)rA * 128 + 2 * tg;
    const float* zB = z + (size_t)rB * 128 + 2 * tg;

    float acc[16][4];
#pragma unroll
    for (int t = 0; t < 16; t++)
#pragma unroll
        for (int u = 0; u < 4; u++) acc[t][u] = 0.f;

    float2 raw0 = *(const float2*)(zA + 0);
    float2 raw1 = *(const float2*)(zB + 0);
    float2 raw2 = *(const float2*)(zA + 8);
    float2 raw3 = *(const float2*)(zB + 8);

#pragma unroll
    for (int ks = 0; ks < 8; ks++) {
        float2 n0v, n1v, n2v, n3v;
        if (ks < 7) {
            n0v = *(const float2*)(zA + 16 * (ks + 1));
            n1v = *(const float2*)(zB + 16 * (ks + 1));
            n2v = *(const float2*)(zA + 16 * (ks + 1) + 8);
            n3v = *(const float2*)(zB + 16 * (ks + 1) + 8);
        }
        uint32_t ah0, al0, ah1, al1, ah2, al2, ah3, al3;
        bf16_split(raw0.x, raw0.y, ah0, al0);
        bf16_split(raw1.x, raw1.y, ah1, al1);
        bf16_split(raw2.x, raw2.y, ah2, al2);
        bf16_split(raw3.x, raw3.y, ah3, al3);

        const uint32_t kadd = (uint32_t)ks * 32;
#pragma unroll
        for (int tp = 0; tp < 8; tp++) {
            const uint32_t toff = (uint32_t)tp * (16 * WK_PITCH * 2) + kadd;
            uint32_t wb0, wb1, wb2, wb3, vb0, vb1, vb2, vb3;
            ldmatrix_x4(wb0, wb1, wb2, wb3, aWH + toff);
            ldmatrix_x4(vb0, vb1, vb2, vb3, aWL + toff);
            float* d0 = acc[2 * tp];
            float* d1 = acc[2 * tp + 1];
            mma_bf16(d0, ah0, ah1, ah2, ah3, wb0, wb1);
            mma_bf16(d1, ah0, ah1, ah2, ah3, wb2, wb3);
            mma_bf16(d0, al0, al1, al2, al3, wb0, wb1);
            mma_bf16(d1, al0, al1, al2, al3, wb2, wb3);
            mma_bf16(d0, ah0, ah1, ah2, ah3, vb0, vb1);
            mma_bf16(d1, ah0, ah1, ah2, ah3, vb2, vb3);
        }
        raw0 = n0v; raw1 = n1v; raw2 = n2v; raw3 = n3v;
    }

    // fold b1 into cols < 64 (t < 8): this thread's cols are 8t+2tg, 8t+2tg+1
    float bA[8][2];
#pragma unroll
    for (int t = 0; t < 8; t++) {
        bA[t][0] = b1[8 * t + 2 * tg];
        bA[t][1] = b1[8 * t + 2 * tg + 1];
    }
#pragma unroll
    for (int t = 0; t < 8; t++) {
        acc[t][0] += bA[t][0]; acc[t][1] += bA[t][1];
        acc[t][2] += bA[t][0]; acc[t][3] += bA[t][1];
    }

    if (rowA < n_nodes) {
        float* dst = g_P + (size_t)rowA * 128 + 2 * tg;
#pragma unroll
        for (int t = 0; t < 16; t++)
            *(float2*)(dst + 8 * t) = make_float2(acc[t][0], acc[t][1]);
    }
    if (rowB < n_nodes) {
        float* dst = g_P + (size_t)rowB * 128 + 2 * tg;
#pragma unroll
        for (int t = 0; t < 16; t++)
            *(float2*)(dst + 8 * t) = make_float2(acc[t][2], acc[t][3]);
    }
}

// ---------------------------------------------------------------------------
// Edge kernel: layer 2 on tensor cores (3-pass bf16 hi/lo). b1 pre-folded.
#define HPITCHB 144      // bytes per H row (72 bf16)
__global__ __launch_bounds__(256, 2) void edge_kernel(
    const void* __restrict__ eidx,
    const float* __restrict__ W2, const float* __restrict__ b2,
    const float* __restrict__ W3, const float* __restrict__ b3,
    float* __restrict__ out, int E)
{
    __shared__ __align__(16) __nv_bfloat16 Hh[8][32 * 72];
    __shared__ __align__(16) __nv_bfloat16 Hl[8][32 * 72];
    __shared__ __align__(16) uint32_t whf[1024];
    __shared__ __align__(16) uint32_t wlf[1024];
    __shared__ float w3s[32], b2sm[32];

    const int tid  = threadIdx.x;
    const int lane = tid & 31;
    const int wid  = tid >> 5;
    const int g    = lane >> 2;
    const int tg   = lane & 3;
    const int gw   = (blockIdx.x * blockDim.x + tid) >> 5;
    const int GW   = (gridDim.x * blockDim.x) >> 5;
    const int STRIDE = GW * 32;

    for (int id = tid; id < 1024; id += 256) {
        int l2 = id & 31;
        int r  = (id >> 5) & 1;
        int nt = (id >> 6) & 3;
        int kt = id >> 8;
        int k0 = kt * 16 + 2 * (l2 & 3) + r * 8;
        int n  = nt * 8 + (l2 >> 2);
        float v0 = W2[k0 * 32 + n];
        float v1 = W2[(k0 + 1) * 32 + n];
        uint32_t hi, lo;
        bf16_split(v0, v1, hi, lo);
        whf[id] = hi;
        wlf[id] = lo;
    }
    if (tid < 32) {
        w3s[tid]  = W3[tid];
        b2sm[tid] = b2[tid];
    }
    const float b3v = b3[0];

    const int* ei32 = (const int*)eidx;
    int oddw = ei32[2 * lane + 1] | ei32[2 * lane + 65];
    const bool is64 = (__ballot_sync(0xffffffffu, oddw != 0) == 0u);

    const char* __restrict__ Pb = (const char*)g_P;
    const unsigned lane8 = (unsigned)lane * 8u;
    const int Em1 = E - 1;

    __syncthreads();

    char* __restrict__ Hhw = (char*)&Hh[wid][0];
    char* __restrict__ Hlw = (char*)&Hl[wid][0];
    const uint32_t lbase = (uint32_t)(lane & 15) * HPITCHB + (uint32_t)(lane >> 4) * 16;
    const uint32_t aHh = smem_u32(Hhw) + lbase;
    const uint32_t aHl = smem_u32(Hlw) + lbase;

    float b2q[4][2], w3q[4][2];
#pragma unroll
    for (int nt = 0; nt < 4; nt++)
#pragma unroll
        for (int r = 0; r < 2; r++) {
            int col = nt * 8 + 2 * tg + r;
            b2q[nt][r] = b2sm[col];
            w3q[nt][r] = w3s[col];
        }

    for (int b = gw * 32; b < E; b += STRIDE) {
        // ---- batch index load (coalesced, clamped, pre-scaled byte offs) ----
        int me = min(b + lane, Em1);
        int iS, jS;
        if (is64) {
            iS = (int)((const long long*)eidx)[me] * 512;
            jS = (int)((const long long*)eidx)[(long long)E + me] * 512 + 256;
        } else {
            iS = ((const int*)eidx)[me] * 512;
            jS = ((const int*)eidx)[E + me] * 512 + 256;
        }

        // ---- phase 1: gather + layer1 + bf16 split, 1-group prefetch ----
        u64 pa[4], pb[4];
#pragma unroll
        for (int t = 0; t < 4; t++) {
            unsigned ii = (unsigned)__shfl_sync(0xffffffffu, iS, t);
            unsigned jj = (unsigned)__shfl_sync(0xffffffffu, jS, t);
            pa[t] = *(const u64*)(Pb + ii + lane8);
            pb[t] = *(const u64*)(Pb + jj + lane8);
        }
#pragma unroll
        for (int gq = 0; gq < 8; gq++) {
            u64 npa[4], npb[4];
            if (gq < 7) {
#pragma unroll
                for (int t = 0; t < 4; t++) {
                    int en = (gq + 1) * 4 + t;
                    unsigned ii = (unsigned)__shfl_sync(0xffffffffu, iS, en);
                    unsigned jj = (unsigned)__shfl_sync(0xffffffffu, jS, en);
                    npa[t] = *(const u64*)(Pb + ii + lane8);
                    npb[t] = *(const u64*)(Pb + jj + lane8);
                }
            }
#pragma unroll
            for (int t = 0; t < 4; t++) {
                float hx, hy;
                unpack2(fadd2(pa[t], pb[t]), hx, hy);
                hx = fmaxf(hx, 0.f);
                hy = fmaxf(hy, 0.f);
                uint32_t hi, lo;
                bf16_split(hx, hy, hi, lo);
                int e = gq * 4 + t;
                *(uint32_t*)(Hhw + e * HPITCHB + lane * 4) = hi;
                *(uint32_t*)(Hlw + e * HPITCHB + lane * 4) = lo;
            }
            if (gq < 7) {
#pragma unroll
                for (int t = 0; t < 4; t++) { pa[t] = npa[t]; pb[t] = npb[t]; }
            }
        }
        __syncwarp();

        // ---- phase 2: 32x32x64 GEMM on tensor cores (3-pass) ----
        float D[2][4][4];
#pragma unroll
        for (int mt = 0; mt < 2; mt++)
#pragma unroll
            for (int nt = 0; nt < 4; nt++)
#pragma unroll
                for (int u = 0; u < 4; u++) D[mt][nt][u] = 0.f;

#pragma unroll
        for (int kt = 0; kt < 4; kt++) {
            uint32_t ah[2][4], al[2][4];
            ldmatrix_x4(ah[0][0], ah[0][1], ah[0][2], ah[0][3], aHh + kt * 32);
            ldmatrix_x4(ah[1][0], ah[1][1], ah[1][2], ah[1][3], aHh + 16 * HPITCHB + kt * 32);
            ldmatrix_x4(al[0][0], al[0][1], al[0][2], al[0][3], aHl + kt * 32);
            ldmatrix_x4(al[1][0], al[1][1], al[1][2], al[1][3], aHl + 16 * HPITCHB + kt * 32);
            uint32_t bh[4][2], bl[4][2];
#pragma unroll
            for (int nt = 0; nt < 4; nt++) {
                bh[nt][0] = whf[((kt * 4 + nt) * 2 + 0) * 32 + lane];
                bh[nt][1] = whf[((kt * 4 + nt) * 2 + 1) * 32 + lane];
                bl[nt][0] = wlf[((kt * 4 + nt) * 2 + 0) * 32 + lane];
                bl[nt][1] = wlf[((kt * 4 + nt) * 2 + 1) * 32 + lane];
            }
#pragma unroll
            for (int mt = 0; mt < 2; mt++)
#pragma unroll
                for (int nt = 0; nt < 4; nt++) {
                    mma_bf16(D[mt][nt], ah[mt][0], ah[mt][1], ah[mt][2], ah[mt][3],
                             bh[nt][0], bh[nt][1]);
                    mma_bf16(D[mt][nt], al[mt][0], al[mt][1], al[mt][2], al[mt][3],
                             bh[nt][0], bh[nt][1]);
                    mma_bf16(D[mt][nt], ah[mt][0], ah[mt][1], ah[mt][2], ah[mt][3],
                             bl[nt][0], bl[nt][1]);
                }
        }

        // ---- phase 3: bias+relu, dot w3, 4-lane reduce, sigmoid, store ----
        float part[4] = {0.f, 0.f, 0.f, 0.f};
#pragma unroll
        for (int mt = 0; mt < 2; mt++)
#pragma unroll
            for (int nt = 0; nt < 4; nt++) {
                const float* c = D[mt][nt];
                part[mt * 2 + 0] = fmaf(fmaxf(c[0] + b2q[nt][0], 0.f), w3q[nt][0],
                                   fmaf(fmaxf(c[1] + b2q[nt][1], 0.f), w3q[nt][1],
                                        part[mt * 2 + 0]));
                part[mt * 2 + 1] = fmaf(fmaxf(c[2] + b2q[nt][0], 0.f), w3q[nt][0],
                                   fmaf(fmaxf(c[3] + b2q[nt][1], 0.f), w3q[nt][1],
                                        part[mt * 2 + 1]));
            }
#pragma unroll
        for (int t = 0; t < 4; t++) {
            part[t] += __shfl_xor_sync(0xffffffffu, part[t], 1);
            part[t] += __shfl_xor_sync(0xffffffffu, part[t], 2);
        }
        if (tg == 0) {
#pragma unroll
            for (int t = 0; t < 4; t++) {
                int row = g + t * 8;
                if (b + row < E) {
                    float sig = __fdividef(1.f, 1.f + __expf(-(part[t] + b3v)));
                    out[b + row] = sig;
                }
            }
        }
        __syncwarp();
    }
}

// ---------------------------------------------------------------------------
extern "C" void kernel_launch(void* const* d_in, const int* in_sizes, int n_in,
                              void* d_out, int out_size)
{
    const float* z  = (const float*)d_in[0];
    const void*  ei = d_in[1];
    const float* W1 = (const float*)d_in[2];
    const float* b1 = (const float*)d_in[3];
    const float* W2 = (const float*)d_in[4];
    const float* b2 = (const float*)d_in[5];
    const float* W3 = (const float*)d_in[6];
    const float* b3 = (const float*)d_in[7];
    float* out = (float*)d_out;

    int n_nodes = in_sizes[0] / INDIM;
    if (n_nodes > MAX_NODES) n_nodes = MAX_NODES;
    int E = out_size;

    cudaFuncSetAttribute(precompute_mma_kernel,
                         cudaFuncAttributeMaxDynamicSharedMemorySize, SMEM_PRE);

    w_prep_kernel<<<64, 256>>>(W1);
    int gblocks = (n_nodes + 127) / 128;
    precompute_mma_kernel<<<gblocks, 256, SMEM_PRE>>>(z, b1, n_nodes);
    edge_kernel<<<296, 256>>>(ei, W2, b2, W3, b3, out, E);
}

// round 15
// speedup vs baseline: 1.4368x; 1.0320x over previous
#include <cuda_runtime.h>
#include <cuda_bf16.h>
#include <cstdint>

#define MAX_NODES 100000
#define INDIM 128

typedef unsigned long long u64;

// Scratch: per-node projections P[n][0:64]=z@W1a+b1, P[n][64:128]=z@W1b
__device__ float g_P[MAX_NODES * 128];
// W^T images, bf16 hi/lo, [n=128][k pitch 136]
#define WK_PITCH 136
__device__ __align__(16) __nv_bfloat16 g_wh[128 * WK_PITCH];
__device__ __align__(16) __nv_bfloat16 g_wl[128 * WK_PITCH];
// work-stealing counter for edge kernel (reset by w_prep each launch/replay)
__device__ int g_ctr;

// ---------------------------------------------------------------------------
// f32x2 packed helpers
__device__ __forceinline__ u64 pack2(float lo, float hi) {
    u64 r; asm("mov.b64 %0, {%1, %2};" : "=l"(r) : "f"(lo), "f"(hi)); return r;
}
__device__ __forceinline__ void unpack2(u64 v, float& lo, float& hi) {
    asm("mov.b64 {%0, %1}, %2;" : "=f"(lo), "=f"(hi) : "l"(v));
}
__device__ __forceinline__ u64 fadd2(u64 a, u64 b) {
    u64 r; asm("add.rn.f32x2 %0, %1, %2;" : "=l"(r) : "l"(a), "l"(b)); return r;
}

// ---------------------------------------------------------------------------
// warp-MMA helpers (baseline PTX, plain sm_103 target)
__device__ __forceinline__ void mma_bf16(float* d,
                                         uint32_t a0, uint32_t a1, uint32_t a2, uint32_t a3,
                                         uint32_t b0, uint32_t b1) {
    asm volatile(
        "mma.sync.aligned.m16n8k16.row.col.f32.bf16.bf16.f32 "
        "{%0,%1,%2,%3}, {%4,%5,%6,%7}, {%8,%9}, {%0,%1,%2,%3};"
        : "+f"(d[0]), "+f"(d[1]), "+f"(d[2]), "+f"(d[3])
        : "r"(a0), "r"(a1), "r"(a2), "r"(a3), "r"(b0), "r"(b1));
}
__device__ __forceinline__ void ldmatrix_x4(uint32_t& r0, uint32_t& r1,
                                            uint32_t& r2, uint32_t& r3, uint32_t addr) {
    asm volatile("ldmatrix.sync.aligned.m8n8.x4.shared.b16 {%0,%1,%2,%3}, [%4];"
                 : "=r"(r0), "=r"(r1), "=r"(r2), "=r"(r3) : "r"(addr));
}
__device__ __forceinline__ uint32_t smem_u32(const void* p) {
    uint32_t a;
    asm("{ .reg .u64 t; cvta.to.shared.u64 t, %1; cvt.u32.u64 %0, t; }" : "=r"(a) : "l"(p));
    return a;
}
__device__ __forceinline__ uint32_t bf2(float x, float y) {  // lo=x, hi=y
    __nv_bfloat162 t = __floats2bfloat162_rn(x, y);
    uint32_t r; asm("mov.b32 %0, %1;" : "=r"(r) : "r"(*(uint32_t*)&t)); return r;
}
__device__ __forceinline__ void bf16_split(float x, float y, uint32_t& hi, uint32_t& lo) {
    hi = bf2(x, y);
    float hx = __uint_as_float(hi << 16);
    float hy = __uint_as_float(hi & 0xffff0000u);
    lo = bf2(x - hx, y - hy);
}

// ---------------------------------------------------------------------------
// One-shot W1 prep (parallel) + work-stealing counter reset.
__global__ void w_prep_kernel(const float* __restrict__ W1) {
    if (blockIdx.x == 0 && threadIdx.x == 0) g_ctr = 0;
    int idx = blockIdx.x * 256 + threadIdx.x;
    if (idx < 128 * 128) {
        int n = idx >> 7, k = idx & 127;
        float v = (n < 64) ? W1[k * 64 + n] : W1[(128 + k) * 64 + (n - 64)];
        __nv_bfloat16 h = __float2bfloat16_rn(v);
        __nv_bfloat16 l = __float2bfloat16_rn(v - __bfloat162float(h));
        g_wh[n * WK_PITCH + k] = h;
        g_wl[n * WK_PITCH + k] = l;
    }
}

// ---------------------------------------------------------------------------
// Precompute via warp-level bf16 MMA; b1 folded into epilogue (cols < 64).
#define WIMG_BYTES (128 * WK_PITCH * 2)
#define SMEM_PRE   (2 * WIMG_BYTES)

__global__ __launch_bounds__(256) void precompute_mma_kernel(
    const float* __restrict__ z, const float* __restrict__ b1, int n_nodes)
{
    extern __shared__ __align__(16) char dsm[];
    __nv_bfloat16* swh = (__nv_bfloat16*)dsm;
    __nv_bfloat16* swl = (__nv_bfloat16*)(dsm + WIMG_BYTES);

    const int tid  = threadIdx.x;
    const int wid  = tid >> 5;
    const int lane = tid & 31;
    const int g    = lane >> 2;
    const int tg   = lane & 3;
    const int nb   = blockIdx.x * 128;
    const int r0   = wid * 16;

    {
        const float4* sh = (const float4*)g_wh;
        const float4* sl = (const float4*)g_wl;
        float4* dh = (float4*)swh;
        float4* dl = (float4*)swl;
        for (int i = tid; i < WIMG_BYTES / 16; i += 256) { dh[i] = sh[i]; dl[i] = sl[i]; }
    }
    __syncthreads();

    const int nloc   = (lane & 7) + ((lane >> 4) << 3);
    const int koff16 = (lane >> 3) & 1;
    const uint32_t aWH = smem_u32(swh) + (uint32_t)nloc * (WK_PITCH * 2) + (uint32_t)koff16 * 16;
    const uint32_t aWL = smem_u32(swl) + (uint32_t)nloc * (WK_PITCH * 2) + (uint32_t)koff16 * 16;

    int rowA = nb + r0 + g;
    int rowB = rowA + 8;
    const int rA = (rowA < n_nodes) ? rowA : 0;
    const int rB = (rowB < n_nodes) ? rowB : 0;
    const float* zA = z + (size_t)rA * 128 + 2 * tg;
    const float* zB = z + (size_t)rB * 128 + 2 * tg;

    float acc[16][4];
#pragma unroll
    for (int t = 0; t < 16; t++)
#pragma unroll
        for (int u = 0; u < 4; u++) acc[t][u] = 0.f;

    float2 raw0 = *(const float2*)(zA + 0);
    float2 raw1 = *(const float2*)(zB + 0);
    float2 raw2 = *(const float2*)(zA + 8);
    float2 raw3 = *(const float2*)(zB + 8);

#pragma unroll
    for (int ks = 0; ks < 8; ks++) {
        float2 n0v, n1v, n2v, n3v;
        if (ks < 7) {
            n0v = *(const float2*)(zA + 16 * (ks + 1));
            n1v = *(const float2*)(zB + 16 * (ks + 1));
            n2v = *(const float2*)(zA + 16 * (ks + 1) + 8);
            n3v = *(const float2*)(zB + 16 * (ks + 1) + 8);
        }
        uint32_t ah0, al0, ah1, al1, ah2, al2, ah3, al3;
        bf16_split(raw0.x, raw0.y, ah0, al0);
        bf16_split(raw1.x, raw1.y, ah1, al1);
        bf16_split(raw2.x, raw2.y, ah2, al2);
        bf16_split(raw3.x, raw3.y, ah3, al3);

        const uint32_t kadd = (uint32_t)ks * 32;
#pragma unroll
        for (int tp = 0; tp < 8; tp++) {
            const uint32_t toff = (uint32_t)tp * (16 * WK_PITCH * 2) + kadd;
            uint32_t wb0, wb1, wb2, wb3, vb0, vb1, vb2, vb3;
            ldmatrix_x4(wb0, wb1, wb2, wb3, aWH + toff);
            ldmatrix_x4(vb0, vb1, vb2, vb3, aWL + toff);
            float* d0 = acc[2 * tp];
            float* d1 = acc[2 * tp + 1];
            mma_bf16(d0, ah0, ah1, ah2, ah3, wb0, wb1);
            mma_bf16(d1, ah0, ah1, ah2, ah3, wb2, wb3);
            mma_bf16(d0, al0, al1, al2, al3, wb0, wb1);
            mma_bf16(d1, al0, al1, al2, al3, wb2, wb3);
            mma_bf16(d0, ah0, ah1, ah2, ah3, vb0, vb1);
            mma_bf16(d1, ah0, ah1, ah2, ah3, vb2, vb3);
        }
        raw0 = n0v; raw1 = n1v; raw2 = n2v; raw3 = n3v;
    }

    // fold b1 into cols < 64 (t < 8): this thread's cols are 8t+2tg, 8t+2tg+1
    float bA[8][2];
#pragma unroll
    for (int t = 0; t < 8; t++) {
        bA[t][0] = b1[8 * t + 2 * tg];
        bA[t][1] = b1[8 * t + 2 * tg + 1];
    }
#pragma unroll
    for (int t = 0; t < 8; t++) {
        acc[t][0] += bA[t][0]; acc[t][1] += bA[t][1];
        acc[t][2] += bA[t][0]; acc[t][3] += bA[t][1];
    }

    if (rowA < n_nodes) {
        float* dst = g_P + (size_t)rowA * 128 + 2 * tg;
#pragma unroll
        for (int t = 0; t < 16; t++)
            *(float2*)(dst + 8 * t) = make_float2(acc[t][0], acc[t][1]);
    }
    if (rowB < n_nodes) {
        float* dst = g_P + (size_t)rowB * 128 + 2 * tg;
#pragma unroll
        for (int t = 0; t < 16; t++)
            *(float2*)(dst + 8 * t) = make_float2(acc[t][2], acc[t][3]);
    }
}

// ---------------------------------------------------------------------------
// Edge kernel: layer 2 on tensor cores (3-pass bf16 hi/lo), work-stealing.
#define HPITCHB 144      // bytes per H row (72 bf16)
__global__ __launch_bounds__(256, 2) void edge_kernel(
    const void* __restrict__ eidx,
    const float* __restrict__ W2, const float* __restrict__ b2,
    const float* __restrict__ W3, const float* __restrict__ b3,
    float* __restrict__ out, int E, int nbatch)
{
    __shared__ __align__(16) __nv_bfloat16 Hh[8][32 * 72];
    __shared__ __align__(16) __nv_bfloat16 Hl[8][32 * 72];
    __shared__ __align__(16) ulonglong2 wcb[512];   // [(kt*4+nt)*32+lane] = {(bh0,bh1),(bl0,bl1)}
    __shared__ float w3s[32], b2sm[32];

    const int tid  = threadIdx.x;
    const int lane = tid & 31;
    const int wid  = tid >> 5;
    const int g    = lane >> 2;
    const int tg   = lane & 3;

    // build combined W2 fragment table
    for (int id = tid; id < 512; id += 256) {
        int l2 = id & 31;
        int nt = (id >> 5) & 3;
        int kt = id >> 7;
        int n  = nt * 8 + (l2 >> 2);
        int k0 = kt * 16 + 2 * (l2 & 3);
        float v00 = W2[k0 * 32 + n];
        float v01 = W2[(k0 + 1) * 32 + n];
        float v10 = W2[(k0 + 8) * 32 + n];
        float v11 = W2[(k0 + 9) * 32 + n];
        uint32_t h0, l0, h1, l1;
        bf16_split(v00, v01, h0, l0);
        bf16_split(v10, v11, h1, l1);
        ulonglong2 v;
        v.x = (u64)h0 | ((u64)h1 << 32);
        v.y = (u64)l0 | ((u64)l1 << 32);
        wcb[id] = v;
    }
    if (tid < 32) {
        w3s[tid]  = W3[tid];
        b2sm[tid] = b2[tid];
    }
    const float b3v = b3[0];

    const int* ei32 = (const int*)eidx;
    int oddw = ei32[2 * lane + 1] | ei32[2 * lane + 65];
    const bool is64 = (__ballot_sync(0xffffffffu, oddw != 0) == 0u);

    const char* __restrict__ Pb = (const char*)g_P;
    const unsigned lane8 = (unsigned)lane * 8u;
    const int Em1 = E - 1;

    __syncthreads();

    char* __restrict__ Hhw = (char*)&Hh[wid][0];
    char* __restrict__ Hlw = (char*)&Hl[wid][0];
    const uint32_t lbase = (uint32_t)(lane & 15) * HPITCHB + (uint32_t)(lane >> 4) * 16;
    const uint32_t aHh = smem_u32(Hhw) + lbase;
    const uint32_t aHl = smem_u32(Hlw) + lbase;

    float b2q[4][2], w3q[4][2];
#pragma unroll
    for (int nt = 0; nt < 4; nt++)
#pragma unroll
        for (int r = 0; r < 2; r++) {
            int col = nt * 8 + 2 * tg + r;
            b2q[nt][r] = b2sm[col];
            w3q[nt][r] = w3s[col];
        }

    // work-stealing batch loop (one-ahead prefetch of batch id)
    int cur;
    if (lane == 0) cur = atomicAdd(&g_ctr, 1);
    cur = __shfl_sync(0xffffffffu, cur, 0);

    while (cur < nbatch) {
        int nxt;
        if (lane == 0) nxt = atomicAdd(&g_ctr, 1);
        nxt = __shfl_sync(0xffffffffu, nxt, 0);

        const int b = cur * 32;

        // ---- batch index load (coalesced, clamped, pre-scaled byte offs) ----
        int me = min(b + lane, Em1);
        int iS, jS;
        if (is64) {
            iS = (int)((const long long*)eidx)[me] * 512;
            jS = (int)((const long long*)eidx)[(long long)E + me] * 512 + 256;
        } else {
            iS = ((const int*)eidx)[me] * 512;
            jS = ((const int*)eidx)[E + me] * 512 + 256;
        }

        // ---- phase 1: gather + layer1 + bf16 split, 1-group prefetch ----
        u64 pa[4], pb[4];
#pragma unroll
        for (int t = 0; t < 4; t++) {
            unsigned ii = (unsigned)__shfl_sync(0xffffffffu, iS, t);
            unsigned jj = (unsigned)__shfl_sync(0xffffffffu, jS, t);
            pa[t] = *(const u64*)(Pb + ii + lane8);
            pb[t] = *(const u64*)(Pb + jj + lane8);
        }
#pragma unroll
        for (int gq = 0; gq < 8; gq++) {
            u64 npa[4], npb[4];
            if (gq < 7) {
#pragma unroll
                for (int t = 0; t < 4; t++) {
                    int en = (gq + 1) * 4 + t;
                    unsigned ii = (unsigned)__shfl_sync(0xffffffffu, iS, en);
                    unsigned jj = (unsigned)__shfl_sync(0xffffffffu, jS, en);
                    npa[t] = *(const u64*)(Pb + ii + lane8);
                    npb[t] = *(const u64*)(Pb + jj + lane8);
                }
            }
#pragma unroll
            for (int t = 0; t < 4; t++) {
                float hx, hy;
                unpack2(fadd2(pa[t], pb[t]), hx, hy);
                hx = fmaxf(hx, 0.f);
                hy = fmaxf(hy, 0.f);
                uint32_t hi, lo;
                bf16_split(hx, hy, hi, lo);
                int e = gq * 4 + t;
                *(uint32_t*)(Hhw + e * HPITCHB + lane * 4) = hi;
                *(uint32_t*)(Hlw + e * HPITCHB + lane * 4) = lo;
            }
            if (gq < 7) {
#pragma unroll
                for (int t = 0; t < 4; t++) { pa[t] = npa[t]; pb[t] = npb[t]; }
            }
        }
        __syncwarp();

        // ---- phase 2: 32x32x64 GEMM on tensor cores (3-pass) ----
        float D[2][4][4];
#pragma unroll
        for (int mt = 0; mt < 2; mt++)
#pragma unroll
            for (int nt = 0; nt < 4; nt++)
#pragma unroll
                for (int u = 0; u < 4; u++) D[mt][nt][u] = 0.f;

#pragma unroll
        for (int kt = 0; kt < 4; kt++) {
            uint32_t ah[2][4], al[2][4];
            ldmatrix_x4(ah[0][0], ah[0][1], ah[0][2], ah[0][3], aHh + kt * 32);
            ldmatrix_x4(ah[1][0], ah[1][1], ah[1][2], ah[1][3], aHh + 16 * HPITCHB + kt * 32);
            ldmatrix_x4(al[0][0], al[0][1], al[0][2], al[0][3], aHl + kt * 32);
            ldmatrix_x4(al[1][0], al[1][1], al[1][2], al[1][3], aHl + 16 * HPITCHB + kt * 32);
#pragma unroll
            for (int nt = 0; nt < 4; nt++) {
                ulonglong2 wv = wcb[(kt * 4 + nt) * 32 + lane];
                uint32_t bh0 = (uint32_t)wv.x, bh1 = (uint32_t)(wv.x >> 32);
                uint32_t bl0 = (uint32_t)wv.y, bl1 = (uint32_t)(wv.y >> 32);
#pragma unroll
                for (int mt = 0; mt < 2; mt++) {
                    mma_bf16(D[mt][nt], ah[mt][0], ah[mt][1], ah[mt][2], ah[mt][3], bh0, bh1);
                    mma_bf16(D[mt][nt], al[mt][0], al[mt][1], al[mt][2], al[mt][3], bh0, bh1);
                    mma_bf16(D[mt][nt], ah[mt][0], ah[mt][1], ah[mt][2], ah[mt][3], bl0, bl1);
                }
            }
        }

        // ---- phase 3: bias+relu, dot w3, 4-lane reduce, sigmoid, store ----
        float part[4] = {0.f, 0.f, 0.f, 0.f};
#pragma unroll
        for (int mt = 0; mt < 2; mt++)
#pragma unroll
            for (int nt = 0; nt < 4; nt++) {
                const float* c = D[mt][nt];
                part[mt * 2 + 0] = fmaf(fmaxf(c[0] + b2q[nt][0], 0.f), w3q[nt][0],
                                   fmaf(fmaxf(c[1] + b2q[nt][1], 0.f), w3q[nt][1],
                                        part[mt * 2 + 0]));
                part[mt * 2 + 1] = fmaf(fmaxf(c[2] + b2q[nt][0], 0.f), w3q[nt][0],
                                   fmaf(fmaxf(c[3] + b2q[nt][1], 0.f), w3q[nt][1],
                                        part[mt * 2 + 1]));
            }
#pragma unroll
        for (int t = 0; t < 4; t++) {
            part[t] += __shfl_xor_sync(0xffffffffu, part[t], 1);
            part[t] += __shfl_xor_sync(0xffffffffu, part[t], 2);
        }
        if (tg == 0) {
#pragma unroll
            for (int t = 0; t < 4; t++) {
                int row = g + t * 8;
                if (b + row < E) {
                    float sig = __fdividef(1.f, 1.f + __expf(-(part[t] + b3v)));
                    out[b + row] = sig;
                }
            }
        }
        cur = nxt;
    }
}

// ---------------------------------------------------------------------------
extern "C" void kernel_launch(void* const* d_in, const int* in_sizes, int n_in,
                              void* d_out, int out_size)
{
    const float* z  = (const float*)d_in[0];
    const void*  ei = d_in[1];
    const float* W1 = (const float*)d_in[2];
    const float* b1 = (const float*)d_in[3];
    const float* W2 = (const float*)d_in[4];
    const float* b2 = (const float*)d_in[5];
    const float* W3 = (const float*)d_in[6];
    const float* b3 = (const float*)d_in[7];
    float* out = (float*)d_out;

    int n_nodes = in_sizes[0] / INDIM;
    if (n_nodes > MAX_NODES) n_nodes = MAX_NODES;
    int E = out_size;
    int nbatch = (E + 31) / 32;

    cudaFuncSetAttribute(precompute_mma_kernel,
                         cudaFuncAttributeMaxDynamicSharedMemorySize, SMEM_PRE);

    w_prep_kernel<<<64, 256>>>(W1);
    int gblocks = (n_nodes + 127) / 128;
    precompute_mma_kernel<<<gblocks, 256, SMEM_PRE>>>(z, b1, n_nodes);
    edge_kernel<<<296, 256>>>(ei, W2, b2, W3, b3, out, E, nbatch);
}